// round 14
// baseline (speedup 1.0000x reference)
#include <cuda_runtime.h>

#define HD 64
#define NG 16
#define ETILE 32
#define SST 68            // node-kernel smem stride
#define EST 72            // edge-kernel smem stride
#define EW (64 * SST)
#define EWE (ETILE * EST) // 2304
#define LN_EPS 1e-3f
#define NMAX 100000
#define EDGE_GRID 444     // 148 SMs x 3 CTAs
#define NODE_GRID 296

typedef unsigned long long u64;
typedef unsigned int uint;

__device__ float g_h[NMAX * HD];
__device__ float g_P[NMAX * HD];
__device__ float g_pool[NMAX * HD];
__device__ float g_ctx[NG * HD];

// ---------------- helpers ----------------
__device__ __forceinline__ void redv2(float* p, float x, float y) {
    asm volatile("red.global.add.v2.f32 [%0], {%1,%2};"
                 :: "l"(p), "f"(x), "f"(y) : "memory");
}
__device__ __forceinline__ uint to_tf32(float f) {
    uint r; asm("cvt.rna.tf32.f32 %0, %1;" : "=r"(r) : "f"(f));
    return r;
}
__device__ __forceinline__ void mma_tf32(float c[4], uint a0, uint a1, uint a2, uint a3,
                                         uint b0, uint b1) {
    asm("mma.sync.aligned.m16n8k8.row.col.f32.tf32.tf32.f32 "
        "{%0,%1,%2,%3}, {%4,%5,%6,%7}, {%8,%9}, {%0,%1,%2,%3};"
        : "+f"(c[0]), "+f"(c[1]), "+f"(c[2]), "+f"(c[3])
        : "r"(a0), "r"(a1), "r"(a2), "r"(a3), "r"(b0), "r"(b1));
}
__device__ __forceinline__ void cpa16(uint dst, const void* src) {
    asm volatile("cp.async.ca.shared.global [%0], [%1], 16;" :: "r"(dst), "l"(src));
}
__device__ __forceinline__ void cpg16(uint dst, const void* src) {
    asm volatile("cp.async.cg.shared.global [%0], [%1], 16;" :: "r"(dst), "l"(src));
}
#define CP_COMMIT() asm volatile("cp.async.commit_group;" ::: "memory")
#define CP_WAIT0()  asm volatile("cp.async.wait_group 0;" ::: "memory")
#define CP_WAIT1()  asm volatile("cp.async.wait_group 1;" ::: "memory")

// stage 64x64 W into fragment-ordered tf32 smem (node kernel)
__device__ __forceinline__ void stage_wfrag(const float* __restrict__ W, uint* dst, int t) {
#pragma unroll
    for (int i = 0; i < 16; i++) {
        int flat = t + 256 * i;
        int h = flat & 1, tg = (flat >> 1) & 3, g4 = (flat >> 3) & 7;
        int nt = (flat >> 6) & 7, kk = (flat >> 9) & 7;
        dst[flat] = to_tf32(W[(kk * 8 + tg + 4 * h) * 64 + nt * 8 + g4]);
    }
}

// node-kernel mma mainloop (A stride SST, natural k order)
__device__ __forceinline__ void mma_loop(const uint* __restrict__ X,
                                         const uint* __restrict__ Wf,
                                         int r0, int gid4, int tig, int nb4,
                                         float acc[4][4]) {
    const uint* aR0 = X + (r0 + gid4) * SST;
    const uint* aR1 = aR0 + 8 * SST;
#pragma unroll
    for (int kk = 0; kk < 8; kk++) {
        int ca = kk * 8 + tig;
        uint a0 = aR0[ca], a1 = aR1[ca], a2 = aR0[ca + 4], a3 = aR1[ca + 4];
#pragma unroll
        for (int nt = 0; nt < 4; nt++) {
            uint2 b = *(const uint2*)(Wf + ((kk * 8 + nb4 + nt) * 8 + gid4) * 8 + tig * 2);
            mma_tf32(acc[nt], a0, a1, a2, a3, b.x, b.y);
        }
    }
}

// ---------------- fused node kernel (R13 winner, unchanged) ----------------
__global__ __launch_bounds__(256, 2) void k_node_mma(
    const float* __restrict__ hext, int use_gh, int mode,
    const float* __restrict__ Wres, const float* __restrict__ bres,
    const float* __restrict__ gam, const float* __restrict__ bet,
    const float* __restrict__ Wn, const float* __restrict__ bn,
    const int* __restrict__ gid, int N)
{
    extern __shared__ uint sm[];
    uint* sWh = sm;
    uint* sWp = sm + 4096;
    uint* sWn = sm + 8192;
    float* sCtx = (float*)(sm + 8192);
    uint* sH  = sm + 12288;
    uint* sPo = sm + 16640;
    float2* sRed = (float2*)(sm + 20992);

    int t = threadIdx.x;
    const float* hin = use_gh ? g_h : hext;

    if (mode != 0) { stage_wfrag(Wres, sWh, t); stage_wfrag(Wres + 4096, sWp, t); }
    if (mode != 2) stage_wfrag(Wn, sWn, t);
    else
        for (int i = t; i < NG * HD; i += 256) sCtx[i] = 0.f;
    if (mode == 0 && blockIdx.x == 0)
        for (int i = t; i < NG * HD; i += 256) g_ctx[i] = 0.f;

    int lane = t & 31, gid4 = lane >> 2, tig = lane & 3;
    int w = t >> 5, rw = w & 3, nh = w >> 2;
    int r0 = rw * 16, nb4 = nh * 4;

    float2 vb[4], vg[4], vbt[4], vbn[4];
#pragma unroll
    for (int nt = 0; nt < 4; nt++) {
        int c = (nb4 + nt) * 8 + 2 * tig;
        vb[nt]  = *(const float2*)(bres + c);
        vg[nt]  = *(const float2*)(gam + c);
        vbt[nt] = *(const float2*)(bet + c);
        vbn[nt] = *(const float2*)(bn + c);
    }
    __syncthreads();

    uint bH = (uint)__cvta_generic_to_shared(sH);
    uint bP = (uint)__cvta_generic_to_shared(sPo);
    int ntiles = (N + 63) >> 6;

    for (int tile = blockIdx.x; tile < ntiles; tile += gridDim.x) {
        int nb = tile << 6;
        __syncthreads();
#pragma unroll
        for (int i = 0; i < 4; i++) {
            int chunk = t + 256 * i;
            int r = chunk >> 4, c4 = (chunk & 15) * 4;
            int row = nb + r; if (row >= N) row = N - 1;
            cpa16(bH + (uint)((r * SST + c4) * 4), hin + (size_t)row * HD + c4);
            if (mode) cpa16(bP + (uint)((r * SST + c4) * 4), g_pool + (size_t)row * HD + c4);
        }
        CP_COMMIT(); CP_WAIT0(); __syncthreads();

        if (mode != 0) {
            float acc[4][4] = {};
            mma_loop(sH, sWh, r0, gid4, tig, nb4, acc);
            mma_loop(sPo, sWp, r0, gid4, tig, nb4, acc);

            float x[4][4];
            float s[2] = {0.f, 0.f}, s2[2] = {0.f, 0.f};
#pragma unroll
            for (int p = 0; p < 2; p++) {
                int row = r0 + gid4 + 8 * p;
#pragma unroll
                for (int nt = 0; nt < 4; nt++) {
                    int c = (nb4 + nt) * 8 + 2 * tig;
                    float2 hv = *(const float2*)((const float*)sH + row * SST + c);
                    float x0 = fmaxf(acc[nt][2 * p + 0] + hv.x + vb[nt].x, 0.f);
                    float x1 = fmaxf(acc[nt][2 * p + 1] + hv.y + vb[nt].y, 0.f);
                    x[nt][2 * p] = x0; x[nt][2 * p + 1] = x1;
                    s[p] += x0 + x1;
                    s2[p] += x0 * x0 + x1 * x1;
                }
            }
#pragma unroll
            for (int o = 1; o <= 2; o <<= 1) {
#pragma unroll
                for (int p = 0; p < 2; p++) {
                    s[p]  += __shfl_xor_sync(0xffffffffu, s[p], o);
                    s2[p] += __shfl_xor_sync(0xffffffffu, s2[p], o);
                }
            }
            if (tig == 0) {
                sRed[nh * 64 + r0 + gid4]     = make_float2(s[0], s2[0]);
                sRed[nh * 64 + r0 + gid4 + 8] = make_float2(s[1], s2[1]);
            }
            __syncthreads();

            float xn[4][4];
#pragma unroll
            for (int p = 0; p < 2; p++) {
                int row = r0 + gid4 + 8 * p;
                float2 ra = sRed[row], rb = sRed[64 + row];
                float fs = ra.x + rb.x, fs2 = ra.y + rb.y;
                float mean = fs * 0.015625f;
                float var = fmaf(-mean, mean, fs2 * 0.015625f);
                float rsd = rsqrtf(var + LN_EPS);
#pragma unroll
                for (int nt = 0; nt < 4; nt++) {
                    xn[nt][2 * p]     = (x[nt][2 * p] - mean) * rsd * vg[nt].x + vbt[nt].x;
                    xn[nt][2 * p + 1] = (x[nt][2 * p + 1] - mean) * rsd * vg[nt].y + vbt[nt].y;
                }
            }

            if (mode == 1) {
#pragma unroll
                for (int p = 0; p < 2; p++) {
                    int row = r0 + gid4 + 8 * p;
                    int n = nb + row;
#pragma unroll
                    for (int nt = 0; nt < 4; nt++) {
                        int c = (nb4 + nt) * 8 + 2 * tig;
                        if (n < N)
                            *(float2*)(g_h + (size_t)n * HD + c) =
                                make_float2(xn[nt][2 * p], xn[nt][2 * p + 1]);
                        *(float2*)((float*)sH + row * SST + c) =
                            make_float2(xn[nt][2 * p], xn[nt][2 * p + 1]);
                    }
                }
                __syncthreads();
            } else {
                int gfirst = gid[nb];
                int nlast = nb + 63; if (nlast >= N) nlast = N - 1;
                int glast = gid[nlast];
                if (gfirst == glast && nb + 64 <= N) {
#pragma unroll
                    for (int nt = 0; nt < 4; nt++) {
                        float xs0 = xn[nt][0] + xn[nt][2];
                        float xs1 = xn[nt][1] + xn[nt][3];
#pragma unroll
                        for (int o = 4; o <= 16; o <<= 1) {
                            xs0 += __shfl_xor_sync(0xffffffffu, xs0, o);
                            xs1 += __shfl_xor_sync(0xffffffffu, xs1, o);
                        }
                        if (gid4 == 0) {
                            int c = (nb4 + nt) * 8 + 2 * tig;
                            atomicAdd(&sCtx[gfirst * HD + c], xs0);
                            atomicAdd(&sCtx[gfirst * HD + c + 1], xs1);
                        }
                    }
                } else {
#pragma unroll
                    for (int p = 0; p < 2; p++) {
                        int n = nb + r0 + gid4 + 8 * p;
                        if (n < N) {
                            int g = gid[n];
#pragma unroll
                            for (int nt = 0; nt < 4; nt++) {
                                int c = (nb4 + nt) * 8 + 2 * tig;
                                atomicAdd(&sCtx[g * HD + c], xn[nt][2 * p]);
                                atomicAdd(&sCtx[g * HD + c + 1], xn[nt][2 * p + 1]);
                            }
                        }
                    }
                }
            }
        }

        if (mode != 2) {
            float acc2[4][4] = {};
            mma_loop(sH, sWn, r0, gid4, tig, nb4, acc2);
#pragma unroll
            for (int p = 0; p < 2; p++) {
                int row = r0 + gid4 + 8 * p;
                int n = nb + row;
                if (n < N) {
#pragma unroll
                    for (int nt = 0; nt < 4; nt++) {
                        int c = (nb4 + nt) * 8 + 2 * tig;
                        *(float2*)(g_P + (size_t)n * HD + c) =
                            make_float2(acc2[nt][2 * p] + vbn[nt].x,
                                        acc2[nt][2 * p + 1] + vbn[nt].y);
                    }
                }
            }
#pragma unroll
            for (int i = 0; i < 4; i++) {
                int id = t + 256 * i;
                int r = id >> 4, c4 = (id & 15) * 4;
                int n = nb + r;
                if (n < N)
                    *(float4*)(g_pool + (size_t)n * HD + c4) = make_float4(0.f, 0.f, 0.f, 0.f);
            }
        }
    }

    if (mode == 2) {
        __syncthreads();
        for (int i = t; i < NG * HD; i += 256) {
            float v = sCtx[i];
            if (v != 0.f) atomicAdd(&g_ctx[i], v);
        }
    }
}

// ---------------- edge kernel: ETILE=32, 2-nt warps, 3 CTAs/SM ----------------
__global__ __launch_bounds__(256, 3) void k_edge(
    const float* __restrict__ emb, const int* __restrict__ esrc,
    const int* __restrict__ etgt, const float* __restrict__ W2,
    int E, int N)
{
    extern __shared__ uint dsm[];
    uint*  sA  = dsm;                       // [3][EWE] emb raw fp32 bits
    float* sP  = (float*)(dsm + 3 * EWE);   // [3][EWE] gathered P rows
    int*   sid = (int*)(dsm + 6 * EWE);     // [8][64]: src(32), tgt(32)

    int t = threadIdx.x;
    uint bA = (uint)__cvta_generic_to_shared(sA);
    uint bP = (uint)__cvta_generic_to_shared(sP);
    uint bI = (uint)__cvta_generic_to_shared(sid);

    int lane = t & 31;
    int gid4 = lane >> 2;
    int tig  = lane & 3;
    int w    = t >> 5;
    int r0   = (w & 1) * 16;   // row group (0 or 16)
    int nb2  = (w >> 1) * 2;   // nt base, 2 nts per warp

    // stage W2 (coalesced) into smem scratch, then pull this warp's 2-nt fragments
    // to registers. k relabelled: thread tig holds k = {2tig, 2tig+1} per kk.
    {
        uint* scratch = dsm;   // 4096 uints (16 KB) fits in sA region (27.6 KB)
#pragma unroll
        for (int i = 0; i < 16; i++) scratch[t + 256 * i] = __float_as_uint(W2[t + 256 * i]);
        __syncthreads();
    }
    uint2 wB[8][2];
#pragma unroll
    for (int kk = 0; kk < 8; kk++)
#pragma unroll
        for (int nt = 0; nt < 2; nt++) {
            int n = (nb2 + nt) * 8 + gid4;
            wB[kk][nt].x = to_tf32(__uint_as_float(dsm[(kk * 8 + 2 * tig) * 64 + n]));
            wB[kk][nt].y = to_tf32(__uint_as_float(dsm[(kk * 8 + 2 * tig + 1) * 64 + n]));
        }
    __syncthreads();

    int ntiles = (E + ETILE - 1) / ETILE;
    int bid = blockIdx.x, grid = gridDim.x;

    auto stage_ids = [&](int jj) {
        int tile = bid + jj * grid;
        if (tile >= ntiles) return;
        int eb = tile * ETILE;
        int slot = jj & 7;
        if (eb + ETILE <= E) {
            if (t < 8)        cpa16(bI + (uint)((slot * 64 + 4 * t) * 4), esrc + eb + 4 * t);
            else if (t < 16)  cpa16(bI + (uint)((slot * 64 + 32 + 4 * (t - 8)) * 4),
                                    etgt + eb + 4 * (t - 8));
        } else if (t < 32) {
            int e = eb + t;
            sid[slot * 64 + t]      = (e < E) ? esrc[e] : 0;
            sid[slot * 64 + 32 + t] = (e < E) ? etgt[e] : 0;
        }
    };
    auto stage_data = [&](int jj) {
        int tile = bid + jj * grid;
        if (tile >= ntiles) return;
        int eb = tile * ETILE;
        int buf = jj % 3, slot = jj & 7;
#pragma unroll
        for (int i = 0; i < 2; i++) {
            int chunk = t + 256 * i;            // 0..511
            int r = chunk >> 4, c4 = (chunk & 15) * 4;
            int row = eb + r; if (row >= E) row = E - 1;
            cpg16(bA + (uint)((buf * EWE + r * EST + c4) * 4),
                  emb + (size_t)row * HD + c4);
            int s = sid[slot * 64 + r];
            if ((uint)s >= (uint)N) s = 0;
            cpg16(bP + (uint)((buf * EWE + r * EST + c4) * 4),
                  g_P + (size_t)s * HD + c4);
        }
    };

    stage_ids(0); stage_ids(1); CP_COMMIT();
    CP_WAIT0(); __syncthreads();
    stage_data(0); stage_ids(2); CP_COMMIT();
    stage_data(1); stage_ids(3); CP_COMMIT();

    for (int j = 0; ; j++) {
        int tile = bid + j * grid;
        if (tile >= ntiles) break;
        CP_WAIT1();
        __syncthreads();
        stage_data(j + 2); stage_ids(j + 4); CP_COMMIT();

        int eb = tile * ETILE;
        const uint*  A = sA + (j % 3) * EWE;
        const float* P = sP + (j % 3) * EWE;
        const int*   id = sid + (j & 7) * 64;

        float acc[2][4] = {};
        const uint* aR0 = A + (r0 + gid4) * EST;
        const uint* aR1 = aR0 + 8 * EST;
#pragma unroll
        for (int kk = 0; kk < 8; kk++) {
            int ca = kk * 8 + 2 * tig;
            uint2 A0 = *(const uint2*)(aR0 + ca);
            uint2 A1 = *(const uint2*)(aR1 + ca);
            mma_tf32(acc[0], A0.x, A1.x, A0.y, A1.y, wB[kk][0].x, wB[kk][0].y);
            mma_tf32(acc[1], A0.x, A1.x, A0.y, A1.y, wB[kk][1].x, wB[kk][1].y);
        }

#pragma unroll
        for (int p = 0; p < 2; p++) {
            int row = r0 + gid4 + 8 * p;
            if (eb + row < E) {
                int g = id[32 + row];
                float* Pg = g_pool + (size_t)g * HD;
                const float* Ps = P + row * EST;
#pragma unroll
                for (int nt = 0; nt < 2; nt++) {
                    int col = (nb2 + nt) * 8 + 2 * tig;
                    float2 pv = *(const float2*)(Ps + col);
                    float m0 = fmaxf(acc[nt][2 * p + 0] + pv.x, 0.f);
                    float m1 = fmaxf(acc[nt][2 * p + 1] + pv.y, 0.f);
                    redv2(Pg + col, m0, m1);
                }
            }
        }
    }
}

// K5: divide by counts
__global__ void k_final(const int* __restrict__ gid, float* __restrict__ out, int N) {
    int t = threadIdx.x;
    int g = t >> 6;
    int lo = 0, hi = N;
    while (lo < hi) { int m = (lo + hi) >> 1; if (gid[m] < g) lo = m + 1; else hi = m; }
    int lo2 = lo, hi2 = N;
    while (lo2 < hi2) { int m = (lo2 + hi2) >> 1; if (gid[m] < g + 1) lo2 = m + 1; else hi2 = m; }
    float c = (float)(hi2 - lo);
    out[t] = g_ctx[t] / fmaxf(c, 1.f);
}

extern "C" void kernel_launch(void* const* d_in, const int* in_sizes, int n_in,
                              void* d_out, int out_size) {
    const float* h0    = (const float*)d_in[0];
    const float* emb   = (const float*)d_in[1];
    const int*   esrc  = (const int*)d_in[2];
    const int*   etgt  = (const int*)d_in[3];
    const int*   gid   = (const int*)d_in[4];
    const float* Wmsg  = (const float*)d_in[5];
    const float* bmsg  = (const float*)d_in[6];
    const float* Wres  = (const float*)d_in[7];
    const float* bres  = (const float*)d_in[8];
    const float* gamma = (const float*)d_in[9];
    const float* beta  = (const float*)d_in[10];
    float* out = (float*)d_out;

    int N = in_sizes[0] / HD;
    int E = in_sizes[1] / HD;
    const int EDGE_SMEM = 6 * EWE * 4 + 8 * 64 * 4;   // 57344 B
    const int NODE_SMEM = 21248 * 4;                  // 84992 B

    cudaFuncSetAttribute(k_edge, cudaFuncAttributeMaxDynamicSharedMemorySize, EDGE_SMEM);
    cudaFuncSetAttribute(k_node_mma, cudaFuncAttributeMaxDynamicSharedMemorySize, NODE_SMEM);

    // hop 0
    k_node_mma<<<NODE_GRID, 256, NODE_SMEM>>>(h0, 0, 0,
        Wres, bres, gamma, beta, Wmsg, bmsg, gid, N);
    k_edge<<<EDGE_GRID, 256, EDGE_SMEM>>>(emb, esrc, etgt, Wmsg + 4096, E, N);
    k_node_mma<<<NODE_GRID, 256, NODE_SMEM>>>(h0, 0, 1,
        Wres, bres, gamma, beta, Wmsg + 8192, bmsg + 64, gid, N);
    // hop 1
    k_edge<<<EDGE_GRID, 256, EDGE_SMEM>>>(emb, esrc, etgt, Wmsg + 8192 + 4096, E, N);
    k_node_mma<<<NODE_GRID, 256, NODE_SMEM>>>(nullptr, 1, 2,
        Wres + 8192, bres + 64, gamma, beta, Wmsg, bmsg, gid, N);
    // finalize
    k_final<<<1, 1024>>>(gid, out, N);
}

// round 15
// speedup vs baseline: 1.0492x; 1.0492x over previous
#include <cuda_runtime.h>

#define HD 64
#define NG 16
#define ETILE 64
#define SST 68            // node-kernel smem stride
#define EST 72            // edge-kernel smem stride
#define EW (64 * SST)
#define EWE (ETILE * EST) // 4608
#define LN_EPS 1e-3f
#define NMAX 100000
#define EDGE_GRID 296
#define NODE_GRID 296

typedef unsigned long long u64;
typedef unsigned int uint;

__device__ float g_h[NMAX * HD];
__device__ float g_P[NMAX * HD];
__device__ float g_pool[NMAX * HD];
__device__ float g_ctx[NG * HD];

// ---------------- helpers ----------------
__device__ __forceinline__ void redv4(float* p, float4 v) {
    asm volatile("red.global.add.v4.f32 [%0], {%1,%2,%3,%4};"
                 :: "l"(p), "f"(v.x), "f"(v.y), "f"(v.z), "f"(v.w) : "memory");
}
__device__ __forceinline__ uint to_tf32(float f) {
    uint r; asm("cvt.rna.tf32.f32 %0, %1;" : "=r"(r) : "f"(f));
    return r;
}
__device__ __forceinline__ void mma_tf32(float c[4], uint a0, uint a1, uint a2, uint a3,
                                         uint b0, uint b1) {
    asm("mma.sync.aligned.m16n8k8.row.col.f32.tf32.tf32.f32 "
        "{%0,%1,%2,%3}, {%4,%5,%6,%7}, {%8,%9}, {%0,%1,%2,%3};"
        : "+f"(c[0]), "+f"(c[1]), "+f"(c[2]), "+f"(c[3])
        : "r"(a0), "r"(a1), "r"(a2), "r"(a3), "r"(b0), "r"(b1));
}
__device__ __forceinline__ void cpa16(uint dst, const void* src) {
    asm volatile("cp.async.ca.shared.global [%0], [%1], 16;" :: "r"(dst), "l"(src));
}
__device__ __forceinline__ void cpg16(uint dst, const void* src) {
    asm volatile("cp.async.cg.shared.global [%0], [%1], 16;" :: "r"(dst), "l"(src));
}
#define CP_COMMIT() asm volatile("cp.async.commit_group;" ::: "memory")
#define CP_WAIT0()  asm volatile("cp.async.wait_group 0;" ::: "memory")
#define CP_WAIT1()  asm volatile("cp.async.wait_group 1;" ::: "memory")

// stage 64x64 W into fragment-ordered tf32 smem (node kernel)
__device__ __forceinline__ void stage_wfrag(const float* __restrict__ W, uint* dst, int t) {
#pragma unroll
    for (int i = 0; i < 16; i++) {
        int flat = t + 256 * i;
        int h = flat & 1, tg = (flat >> 1) & 3, g4 = (flat >> 3) & 7;
        int nt = (flat >> 6) & 7, kk = (flat >> 9) & 7;
        dst[flat] = to_tf32(W[(kk * 8 + tg + 4 * h) * 64 + nt * 8 + g4]);
    }
}

// node-kernel mma mainloop (A stride SST, natural k order)
__device__ __forceinline__ void mma_loop(const uint* __restrict__ X,
                                         const uint* __restrict__ Wf,
                                         int r0, int gid4, int tig, int nb4,
                                         float acc[4][4]) {
    const uint* aR0 = X + (r0 + gid4) * SST;
    const uint* aR1 = aR0 + 8 * SST;
#pragma unroll
    for (int kk = 0; kk < 8; kk++) {
        int ca = kk * 8 + tig;
        uint a0 = aR0[ca], a1 = aR1[ca], a2 = aR0[ca + 4], a3 = aR1[ca + 4];
#pragma unroll
        for (int nt = 0; nt < 4; nt++) {
            uint2 b = *(const uint2*)(Wf + ((kk * 8 + nb4 + nt) * 8 + gid4) * 8 + tig * 2);
            mma_tf32(acc[nt], a0, a1, a2, a3, b.x, b.y);
        }
    }
}

// ---------------- fused node kernel (R13 winner, unchanged) ----------------
__global__ __launch_bounds__(256, 2) void k_node_mma(
    const float* __restrict__ hext, int use_gh, int mode,
    const float* __restrict__ Wres, const float* __restrict__ bres,
    const float* __restrict__ gam, const float* __restrict__ bet,
    const float* __restrict__ Wn, const float* __restrict__ bn,
    const int* __restrict__ gid, int N)
{
    extern __shared__ uint sm[];
    uint* sWh = sm;
    uint* sWp = sm + 4096;
    uint* sWn = sm + 8192;
    float* sCtx = (float*)(sm + 8192);
    uint* sH  = sm + 12288;
    uint* sPo = sm + 16640;
    float2* sRed = (float2*)(sm + 20992);

    int t = threadIdx.x;
    const float* hin = use_gh ? g_h : hext;

    if (mode != 0) { stage_wfrag(Wres, sWh, t); stage_wfrag(Wres + 4096, sWp, t); }
    if (mode != 2) stage_wfrag(Wn, sWn, t);
    else
        for (int i = t; i < NG * HD; i += 256) sCtx[i] = 0.f;
    if (mode == 0 && blockIdx.x == 0)
        for (int i = t; i < NG * HD; i += 256) g_ctx[i] = 0.f;

    int lane = t & 31, gid4 = lane >> 2, tig = lane & 3;
    int w = t >> 5, rw = w & 3, nh = w >> 2;
    int r0 = rw * 16, nb4 = nh * 4;

    float2 vb[4], vg[4], vbt[4], vbn[4];
#pragma unroll
    for (int nt = 0; nt < 4; nt++) {
        int c = (nb4 + nt) * 8 + 2 * tig;
        vb[nt]  = *(const float2*)(bres + c);
        vg[nt]  = *(const float2*)(gam + c);
        vbt[nt] = *(const float2*)(bet + c);
        vbn[nt] = *(const float2*)(bn + c);
    }
    __syncthreads();

    uint bH = (uint)__cvta_generic_to_shared(sH);
    uint bP = (uint)__cvta_generic_to_shared(sPo);
    int ntiles = (N + 63) >> 6;

    for (int tile = blockIdx.x; tile < ntiles; tile += gridDim.x) {
        int nb = tile << 6;
        __syncthreads();
#pragma unroll
        for (int i = 0; i < 4; i++) {
            int chunk = t + 256 * i;
            int r = chunk >> 4, c4 = (chunk & 15) * 4;
            int row = nb + r; if (row >= N) row = N - 1;
            cpa16(bH + (uint)((r * SST + c4) * 4), hin + (size_t)row * HD + c4);
            if (mode) cpa16(bP + (uint)((r * SST + c4) * 4), g_pool + (size_t)row * HD + c4);
        }
        CP_COMMIT(); CP_WAIT0(); __syncthreads();

        if (mode != 0) {
            float acc[4][4] = {};
            mma_loop(sH, sWh, r0, gid4, tig, nb4, acc);
            mma_loop(sPo, sWp, r0, gid4, tig, nb4, acc);

            float x[4][4];
            float s[2] = {0.f, 0.f}, s2[2] = {0.f, 0.f};
#pragma unroll
            for (int p = 0; p < 2; p++) {
                int row = r0 + gid4 + 8 * p;
#pragma unroll
                for (int nt = 0; nt < 4; nt++) {
                    int c = (nb4 + nt) * 8 + 2 * tig;
                    float2 hv = *(const float2*)((const float*)sH + row * SST + c);
                    float x0 = fmaxf(acc[nt][2 * p + 0] + hv.x + vb[nt].x, 0.f);
                    float x1 = fmaxf(acc[nt][2 * p + 1] + hv.y + vb[nt].y, 0.f);
                    x[nt][2 * p] = x0; x[nt][2 * p + 1] = x1;
                    s[p] += x0 + x1;
                    s2[p] += x0 * x0 + x1 * x1;
                }
            }
#pragma unroll
            for (int o = 1; o <= 2; o <<= 1) {
#pragma unroll
                for (int p = 0; p < 2; p++) {
                    s[p]  += __shfl_xor_sync(0xffffffffu, s[p], o);
                    s2[p] += __shfl_xor_sync(0xffffffffu, s2[p], o);
                }
            }
            if (tig == 0) {
                sRed[nh * 64 + r0 + gid4]     = make_float2(s[0], s2[0]);
                sRed[nh * 64 + r0 + gid4 + 8] = make_float2(s[1], s2[1]);
            }
            __syncthreads();

            float xn[4][4];
#pragma unroll
            for (int p = 0; p < 2; p++) {
                int row = r0 + gid4 + 8 * p;
                float2 ra = sRed[row], rb = sRed[64 + row];
                float fs = ra.x + rb.x, fs2 = ra.y + rb.y;
                float mean = fs * 0.015625f;
                float var = fmaf(-mean, mean, fs2 * 0.015625f);
                float rsd = rsqrtf(var + LN_EPS);
#pragma unroll
                for (int nt = 0; nt < 4; nt++) {
                    xn[nt][2 * p]     = (x[nt][2 * p] - mean) * rsd * vg[nt].x + vbt[nt].x;
                    xn[nt][2 * p + 1] = (x[nt][2 * p + 1] - mean) * rsd * vg[nt].y + vbt[nt].y;
                }
            }

            if (mode == 1) {
#pragma unroll
                for (int p = 0; p < 2; p++) {
                    int row = r0 + gid4 + 8 * p;
                    int n = nb + row;
#pragma unroll
                    for (int nt = 0; nt < 4; nt++) {
                        int c = (nb4 + nt) * 8 + 2 * tig;
                        if (n < N)
                            *(float2*)(g_h + (size_t)n * HD + c) =
                                make_float2(xn[nt][2 * p], xn[nt][2 * p + 1]);
                        *(float2*)((float*)sH + row * SST + c) =
                            make_float2(xn[nt][2 * p], xn[nt][2 * p + 1]);
                    }
                }
                __syncthreads();
            } else {
                int gfirst = gid[nb];
                int nlast = nb + 63; if (nlast >= N) nlast = N - 1;
                int glast = gid[nlast];
                if (gfirst == glast && nb + 64 <= N) {
#pragma unroll
                    for (int nt = 0; nt < 4; nt++) {
                        float xs0 = xn[nt][0] + xn[nt][2];
                        float xs1 = xn[nt][1] + xn[nt][3];
#pragma unroll
                        for (int o = 4; o <= 16; o <<= 1) {
                            xs0 += __shfl_xor_sync(0xffffffffu, xs0, o);
                            xs1 += __shfl_xor_sync(0xffffffffu, xs1, o);
                        }
                        if (gid4 == 0) {
                            int c = (nb4 + nt) * 8 + 2 * tig;
                            atomicAdd(&sCtx[gfirst * HD + c], xs0);
                            atomicAdd(&sCtx[gfirst * HD + c + 1], xs1);
                        }
                    }
                } else {
#pragma unroll
                    for (int p = 0; p < 2; p++) {
                        int n = nb + r0 + gid4 + 8 * p;
                        if (n < N) {
                            int g = gid[n];
#pragma unroll
                            for (int nt = 0; nt < 4; nt++) {
                                int c = (nb4 + nt) * 8 + 2 * tig;
                                atomicAdd(&sCtx[g * HD + c], xn[nt][2 * p]);
                                atomicAdd(&sCtx[g * HD + c + 1], xn[nt][2 * p + 1]);
                            }
                        }
                    }
                }
            }
        }

        if (mode != 2) {
            float acc2[4][4] = {};
            mma_loop(sH, sWn, r0, gid4, tig, nb4, acc2);
#pragma unroll
            for (int p = 0; p < 2; p++) {
                int row = r0 + gid4 + 8 * p;
                int n = nb + row;
                if (n < N) {
#pragma unroll
                    for (int nt = 0; nt < 4; nt++) {
                        int c = (nb4 + nt) * 8 + 2 * tig;
                        *(float2*)(g_P + (size_t)n * HD + c) =
                            make_float2(acc2[nt][2 * p] + vbn[nt].x,
                                        acc2[nt][2 * p + 1] + vbn[nt].y);
                    }
                }
            }
#pragma unroll
            for (int i = 0; i < 4; i++) {
                int id = t + 256 * i;
                int r = id >> 4, c4 = (id & 15) * 4;
                int n = nb + r;
                if (n < N)
                    *(float4*)(g_pool + (size_t)n * HD + c4) = make_float4(0.f, 0.f, 0.f, 0.f);
            }
        }
    }

    if (mode == 2) {
        __syncthreads();
        for (int i = t; i < NG * HD; i += 256) {
            float v = sCtx[i];
            if (v != 0.f) atomicAdd(&g_ctx[i], v);
        }
    }
}

// ---------------- edge kernel: R11 shape + column-permuted tiles -> red.v4 epilogue ----
// Tile T (=nb4+nt), local col j maps to global col:
//   G(T,j) = 32*(T>>2) + 8*(j>>1) + 2*(T&3) + (j&1)
// so thread tig's outputs over nt=0..3 cover contiguous cols 32*(nb4>>2)+8*tig .. +7.
__global__ __launch_bounds__(256, 2) void k_edge(
    const float* __restrict__ emb, const int* __restrict__ esrc,
    const int* __restrict__ etgt, const float* __restrict__ W2,
    int E, int N)
{
    extern __shared__ uint dsm[];
    uint*  sA  = dsm;                       // [3][EWE] emb raw fp32 bits
    float* sP  = (float*)(dsm + 3 * EWE);   // [3][EWE] gathered P rows
    int*   sid = (int*)(dsm + 6 * EWE);     // [8][128]: src(64), tgt(64)

    int t = threadIdx.x;
    uint bA = (uint)__cvta_generic_to_shared(sA);
    uint bP = (uint)__cvta_generic_to_shared(sP);
    uint bI = (uint)__cvta_generic_to_shared(sid);

    int lane = t & 31;
    int gid4 = lane >> 2;
    int tig  = lane & 3;
    int w    = t >> 5;
    int r0   = (w & 3) * 16;
    int nb4  = (w >> 2) * 4;
    int half = (nb4 >> 2) * 32;     // warp's 32-col half base
    int colbase = half + 8 * tig;   // thread's contiguous 8-col base

    // stage W2 (coalesced) into smem scratch, pull permuted fragments to registers.
    {
        uint* scratch = dsm;
#pragma unroll
        for (int i = 0; i < 16; i++) scratch[t + 256 * i] = __float_as_uint(W2[t + 256 * i]);
        __syncthreads();
    }
    uint2 wB[8][4];
#pragma unroll
    for (int kk = 0; kk < 8; kk++)
#pragma unroll
        for (int nt = 0; nt < 4; nt++) {
            // B fragment local n = gid4 -> global col G(nb4+nt, gid4)
            int n = half + 8 * (gid4 >> 1) + 2 * nt + (gid4 & 1);
            wB[kk][nt].x = to_tf32(__uint_as_float(dsm[(kk * 8 + 2 * tig) * 64 + n]));
            wB[kk][nt].y = to_tf32(__uint_as_float(dsm[(kk * 8 + 2 * tig + 1) * 64 + n]));
        }
    __syncthreads();

    int ntiles = (E + ETILE - 1) / ETILE;
    int bid = blockIdx.x, grid = gridDim.x;

    auto stage_ids = [&](int jj) {
        int tile = bid + jj * grid;
        if (tile >= ntiles) return;
        int eb = tile * ETILE;
        int slot = jj & 7;
        if (eb + ETILE <= E) {
            if (t < 16)       cpa16(bI + (uint)((slot * 128 + 4 * t) * 4), esrc + eb + 4 * t);
            else if (t < 32)  cpa16(bI + (uint)((slot * 128 + 64 + 4 * (t - 16)) * 4),
                                    etgt + eb + 4 * (t - 16));
        } else if (t < 64) {
            int e = eb + t;
            sid[slot * 128 + t]      = (e < E) ? esrc[e] : 0;
            sid[slot * 128 + 64 + t] = (e < E) ? etgt[e] : 0;
        }
    };
    auto stage_data = [&](int jj) {
        int tile = bid + jj * grid;
        if (tile >= ntiles) return;
        int eb = tile * ETILE;
        int buf = jj % 3, slot = jj & 7;
#pragma unroll
        for (int i = 0; i < 4; i++) {
            int chunk = t + 256 * i;
            int r = chunk >> 4, c4 = (chunk & 15) * 4;
            int row = eb + r; if (row >= E) row = E - 1;
            cpg16(bA + (uint)((buf * EWE + r * EST + c4) * 4),
                  emb + (size_t)row * HD + c4);
            int s = sid[slot * 128 + r];
            if ((uint)s >= (uint)N) s = 0;
            cpg16(bP + (uint)((buf * EWE + r * EST + c4) * 4),
                  g_P + (size_t)s * HD + c4);
        }
    };

    stage_ids(0); stage_ids(1); CP_COMMIT();
    CP_WAIT0(); __syncthreads();
    stage_data(0); stage_ids(2); CP_COMMIT();
    stage_data(1); stage_ids(3); CP_COMMIT();

    for (int j = 0; ; j++) {
        int tile = bid + j * grid;
        if (tile >= ntiles) break;
        CP_WAIT1();
        __syncthreads();
        stage_data(j + 2); stage_ids(j + 4); CP_COMMIT();

        int eb = tile * ETILE;
        const uint*  A = sA + (j % 3) * EWE;
        const float* P = sP + (j % 3) * EWE;
        const int*   id = sid + (j & 7) * 128;

        float acc[4][4] = {};
        const uint* aR0 = A + (r0 + gid4) * EST;
        const uint* aR1 = aR0 + 8 * EST;
#pragma unroll
        for (int kk = 0; kk < 8; kk++) {
            int ca = kk * 8 + 2 * tig;
            uint2 A0 = *(const uint2*)(aR0 + ca);
            uint2 A1 = *(const uint2*)(aR1 + ca);
#pragma unroll
            for (int nt = 0; nt < 4; nt++)
                mma_tf32(acc[nt], A0.x, A1.x, A0.y, A1.y, wB[kk][nt].x, wB[kk][nt].y);
        }

        // epilogue: thread owns 8 contiguous cols -> 2x LDS.128 + 2x red.v4 per row
#pragma unroll
        for (int p = 0; p < 2; p++) {
            int row = r0 + gid4 + 8 * p;
            if (eb + row < E) {
                int g = id[64 + row];
                float* Pg = g_pool + (size_t)g * HD + colbase;
                const float* Ps = P + row * EST + colbase;
                float4 pa = *(const float4*)(Ps);
                float4 pb = *(const float4*)(Ps + 4);
                float4 m0 = make_float4(fmaxf(acc[0][2 * p] + pa.x, 0.f),
                                        fmaxf(acc[0][2 * p + 1] + pa.y, 0.f),
                                        fmaxf(acc[1][2 * p] + pa.z, 0.f),
                                        fmaxf(acc[1][2 * p + 1] + pa.w, 0.f));
                float4 m1 = make_float4(fmaxf(acc[2][2 * p] + pb.x, 0.f),
                                        fmaxf(acc[2][2 * p + 1] + pb.y, 0.f),
                                        fmaxf(acc[3][2 * p] + pb.z, 0.f),
                                        fmaxf(acc[3][2 * p + 1] + pb.w, 0.f));
                redv4(Pg, m0);
                redv4(Pg + 4, m1);
            }
        }
    }
}

// K5: divide by counts
__global__ void k_final(const int* __restrict__ gid, float* __restrict__ out, int N) {
    int t = threadIdx.x;
    int g = t >> 6;
    int lo = 0, hi = N;
    while (lo < hi) { int m = (lo + hi) >> 1; if (gid[m] < g) lo = m + 1; else hi = m; }
    int lo2 = lo, hi2 = N;
    while (lo2 < hi2) { int m = (lo2 + hi2) >> 1; if (gid[m] < g + 1) lo2 = m + 1; else hi2 = m; }
    float c = (float)(hi2 - lo);
    out[t] = g_ctx[t] / fmaxf(c, 1.f);
}

extern "C" void kernel_launch(void* const* d_in, const int* in_sizes, int n_in,
                              void* d_out, int out_size) {
    const float* h0    = (const float*)d_in[0];
    const float* emb   = (const float*)d_in[1];
    const int*   esrc  = (const int*)d_in[2];
    const int*   etgt  = (const int*)d_in[3];
    const int*   gid   = (const int*)d_in[4];
    const float* Wmsg  = (const float*)d_in[5];
    const float* bmsg  = (const float*)d_in[6];
    const float* Wres  = (const float*)d_in[7];
    const float* bres  = (const float*)d_in[8];
    const float* gamma = (const float*)d_in[9];
    const float* beta  = (const float*)d_in[10];
    float* out = (float*)d_out;

    int N = in_sizes[0] / HD;
    int E = in_sizes[1] / HD;
    const int EDGE_SMEM = 6 * EWE * 4 + 8 * 128 * 4;  // 114688 B
    const int NODE_SMEM = 21248 * 4;                  // 84992 B

    cudaFuncSetAttribute(k_edge, cudaFuncAttributeMaxDynamicSharedMemorySize, EDGE_SMEM);
    cudaFuncSetAttribute(k_node_mma, cudaFuncAttributeMaxDynamicSharedMemorySize, NODE_SMEM);

    // hop 0
    k_node_mma<<<NODE_GRID, 256, NODE_SMEM>>>(h0, 0, 0,
        Wres, bres, gamma, beta, Wmsg, bmsg, gid, N);
    k_edge<<<EDGE_GRID, 256, EDGE_SMEM>>>(emb, esrc, etgt, Wmsg + 4096, E, N);
    k_node_mma<<<NODE_GRID, 256, NODE_SMEM>>>(h0, 0, 1,
        Wres, bres, gamma, beta, Wmsg + 8192, bmsg + 64, gid, N);
    // hop 1
    k_edge<<<EDGE_GRID, 256, EDGE_SMEM>>>(emb, esrc, etgt, Wmsg + 8192 + 4096, E, N);
    k_node_mma<<<NODE_GRID, 256, NODE_SMEM>>>(nullptr, 1, 2,
        Wres + 8192, bres + 64, gamma, beta, Wmsg, bmsg, gid, N);
    // finalize
    k_final<<<1, 1024>>>(gid, out, N);
}